// round 16
// baseline (speedup 1.0000x reference)
#include <cuda_runtime.h>
#include <cuda_fp16.h>
#include <cstdint>

#define B_   2
#define N_   8
#define C_   64
#define H_   192
#define W_   256
#define V_   200000
#define HW_  (H_*W_)
#define R_   (N_*HW_)          // 393216
#define ROWS_ (B_*V_)          // 400000
#define OUT_ 128

// Scratch: zero-initialized at module load; gemm re-zeroes what it reads
// (rows with cnt==0 were never written — their writeback is skipped).
__device__ __align__(16) float g_sums[(size_t)ROWS_*C_];   // 102.4 MB
__device__ float g_cnt[ROWS_];
// Always-zero decoy row: cnt==0 rows read from here (L2-hot) instead of DRAM.
__device__ __align__(16) float g_dummy[64];
// Pre-packed fp16 weights: per (n, pi=kc*4+t): uint2(h16x2[kp0], h16x2[kp0+4]).
__device__ __align__(16) uint2 g_wBp[128*16];              // 16 KB

// ---------------- L2 policy / streaming load+store helpers ----------------
__device__ __forceinline__ uint64_t mkpol_first(){
    uint64_t p;
    asm("createpolicy.fractional.L2::evict_first.b64 %0, 1.0;" : "=l"(p));
    return p;
}
__device__ __forceinline__ uint64_t mkpol_last(){
    uint64_t p;
    asm("createpolicy.fractional.L2::evict_last.b64 %0, 1.0;" : "=l"(p));
    return p;
}
__device__ __forceinline__ float ldg_stream(const float* p, uint64_t pol){
    float v;
    asm("ld.global.nc.L2::cache_hint.f32 %0, [%1], %2;" : "=f"(v) : "l"(p), "l"(pol));
    return v;
}
__device__ __forceinline__ unsigned ldg_stream_u32(const unsigned* p, uint64_t pol){
    unsigned v;
    asm("ld.global.nc.L2::cache_hint.u32 %0, [%1], %2;" : "=r"(v) : "l"(p), "l"(pol));
    return v;
}
__device__ __forceinline__ float4 ldg_stream_v4(const float4* p, uint64_t pol){
    float4 v;
    asm("ld.global.nc.L2::cache_hint.v4.f32 {%0,%1,%2,%3}, [%4], %5;"
        : "=f"(v.x), "=f"(v.y), "=f"(v.z), "=f"(v.w) : "l"(p), "l"(pol));
    return v;
}
__device__ __forceinline__ void stg_pol_f32(float* p, float v, uint64_t pol){
    asm volatile("st.global.L2::cache_hint.f32 [%0], %1, %2;"
                 :: "l"(p), "f"(v), "l"(pol) : "memory");
}
__device__ __forceinline__ void stg_pol_v2(float* p, float2 v, uint64_t pol){
    asm volatile("st.global.L2::cache_hint.v2.f32 [%0], {%1,%2}, %3;"
                 :: "l"(p), "f"(v.x), "f"(v.y), "l"(pol) : "memory");
}
__device__ __forceinline__ void red_v4(float* p, float x0, float x1,
                                       float x2, float x3, uint64_t pol){
    asm volatile("red.global.add.L2::cache_hint.v4.f32 [%0], {%1, %2, %3, %4}, %5;"
                 :: "l"(p), "f"(x0), "f"(x1), "f"(x2), "f"(x3), "l"(pol)
                 : "memory");
}

// fp16 m16n8k16, fp32 accumulate.
#define MMA_F16(c, a0,a1,a2,a3, b0,b1)                                        \
    asm volatile("mma.sync.aligned.m16n8k16.row.col.f32.f16.f16.f32 "         \
        "{%0,%1,%2,%3}, {%4,%5,%6,%7}, {%8,%9}, {%0,%1,%2,%3};"               \
        : "+f"((c)[0]), "+f"((c)[1]), "+f"((c)[2]), "+f"((c)[3])              \
        : "r"(a0), "r"(a1), "r"(a2), "r"(a3), "r"(b0), "r"(b1))

// ---------------------------------------------------------------------------
// Kernel 1: rays + masked scatter-add, fused (one thread per pixel).
// Feature loads batched 32-deep into registers (MLP 4 -> 32); reds issued
// after each batch. No occupancy cap: let ptxas take the registers.
// ---------------------------------------------------------------------------
__global__ void __launch_bounds__(256) scatter_rays_kernel(
    const float* __restrict__ feat,
    const int*   __restrict__ vids,
    const unsigned* __restrict__ mask,
    const float* __restrict__ pose,
    const float* __restrict__ intr,
    float* __restrict__ dout)
{
    int idx = blockIdx.x*blockDim.x + threadIdx.x;   // covers exactly B*R
    uint64_t pf = mkpol_first();

    // ---- rays ----
    {
        int w  = idx % W_;
        int h  = (idx / W_) % H_;
        int bn = idx / HW_;
        const float* p  = pose + bn*16;
        const float* it = intr + bn*6;
        float uu = ((float)w - it[2]) / it[0];
        float vv = ((float)h - it[3]) / it[1];
        float dx = p[0]*uu + p[1]*vv + p[2];
        float dy = p[4]*uu + p[5]*vv + p[6];
        float dz = p[8]*uu + p[9]*vv + p[10];
        float rn = rsqrtf(dx*dx + dy*dy + dz*dz);
        stg_pol_f32(dout + 3*idx + 0, dx*rn, pf);
        stg_pol_f32(dout + 3*idx + 1, dy*rn, pf);
        stg_pol_f32(dout + 3*idx + 2, dz*rn, pf);
    }

    // ---- scatter ----
    unsigned m = ldg_stream_u32(mask + idx, pf);     // fp32 1.0 / int32 1: nonzero
    if (__ballot_sync(0xffffffffu, m != 0u) == 0u) return;
    if (m == 0u) return;

    uint64_t pl = mkpol_last();
    int b   = idx / R_;
    int vid = (int)ldg_stream_u32((const unsigned*)(vids + idx), pf);
    asm volatile("red.global.add.L2::cache_hint.f32 [%0], %1, %2;"
                 :: "l"(&g_cnt[b*V_ + vid]), "f"(1.0f), "l"(pl) : "memory");

    int bn = idx / HW_;
    int hw = idx % HW_;
    const float* fp = feat + (size_t)bn*C_*HW_ + hw;
    float* sp = g_sums + (size_t)(b*V_ + vid)*C_;

    float x[32];
    #pragma unroll
    for (int half = 0; half < 2; half++){
        int cb = half*32;
        #pragma unroll
        for (int c = 0; c < 32; c++)
            x[c] = ldg_stream(fp + (size_t)(cb + c)*HW_, pf);
        #pragma unroll
        for (int cg = 0; cg < 8; cg++)
            red_v4(sp + cb + 4*cg, x[4*cg+0], x[4*cg+1], x[4*cg+2], x[4*cg+3], pl);
    }
}

// ---------------------------------------------------------------------------
// Kernel 2: one-shot weight prep — fp16, packed per (n, pi).
// ---------------------------------------------------------------------------
__global__ void prep_kernel(const float* __restrict__ w_fc)
{
    int i = blockIdx.x*blockDim.x + threadIdx.x;   // 2048 = 128n x 16pi
    int n = i >> 4, pi = i & 15;
    int kc = pi >> 2, t = pi & 3;
    int kp0 = kc*8 + t;
    int kp1 = kp0 + 4;
    __half2 h0 = __floats2half2_rn(w_fc[(2*kp0+0)*128 + n], w_fc[(2*kp0+1)*128 + n]);
    __half2 h1 = __floats2half2_rn(w_fc[(2*kp1+0)*128 + n], w_fc[(2*kp1+1)*128 + n]);
    uint2 p;
    p.x = *(uint32_t*)&h0;
    p.y = *(uint32_t*)&h1;
    g_wBp[i] = p;
}

// ---------------------------------------------------------------------------
// Kernel 3: GEMM via fp16 m16n8k16 mma.sync, 2-pass (A hi/lo x B fp16).
// cnt==0 rows: the LOAD stays unconditional (MLP preserved) but its ADDRESS
// is selected to the L2-hot zero decoy -> 38 MB less DRAM read traffic.
// Zero-writeback store predicated on cnt!=0 as in round 15.
// ---------------------------------------------------------------------------
#define SA_STRIDE 36                        // uint2 per row (32 used)
#define SB_STRIDE 20                        // uint2 per n   (16 used)
#define SMEM_A_B    (128*SA_STRIDE*8)       // 36864 B
#define SMEM_B_B    (128*SB_STRIDE*8)       // 20480 B
#define SM_A_OFF    0
#define SM_B_OFF    SMEM_A_B
#define SM_SCNT     (SM_B_OFF + SMEM_B_B)
#define SM_SRAW     (SM_SCNT + 512)
#define SM_SCONF    (SM_SRAW + 512)
#define SM_SW64     (SM_SCONF + 512)
#define SM_SB       (SM_SW64 + 512)
#define SMEM_TOTAL  (SM_SB + 512)           // 59904 B

__global__ void __launch_bounds__(256, 2) gemm_kernel(
    const float* __restrict__ conf,
    const float* __restrict__ w_fc,
    const float* __restrict__ b_fc,
    float* __restrict__ out)
{
    extern __shared__ unsigned char sm[];
    uint2* sA2 = (uint2*)(sm + SM_A_OFF);
    uint2* sB2 = (uint2*)(sm + SM_B_OFF);
    float* scnt  = (float*)(sm + SM_SCNT);   // 1/max(cnt,1)
    float* sraw  = (float*)(sm + SM_SRAW);   // raw cnt (0 => row untouched)
    float* sconf = (float*)(sm + SM_SCONF);
    float* sw64  = (float*)(sm + SM_SW64);
    float* sb    = (float*)(sm + SM_SB);

    int tid = threadIdx.x;
    size_t rowbase = (size_t)blockIdx.x * 128;

    // --- phase 0: scalars (tid<128) + B copy (all threads, coalesced) ---
    if (tid < 128){
        float cv = g_cnt[rowbase + tid];
        if (cv != 0.0f) g_cnt[rowbase + tid] = 0.0f;   // store-side skip only
        sraw[tid]  = cv;
        scnt[tid]  = 1.0f / fmaxf(cv, 1.0f);
        sconf[tid] = conf[rowbase + tid];
        sw64[tid]  = w_fc[64*128 + tid];
        sb[tid]    = b_fc[tid];
    }
    #pragma unroll
    for (int it = 0; it < 8; it++){
        int j = it*256 + tid;              // 2048 uint2
        int n = j >> 4, pi = j & 15;
        sB2[n*SB_STRIDE + pi] = g_wBp[j];
    }
    __syncthreads();

    // --- phase 1: stage A (scale by 1/cnt, fp16 hi/lo split); zero g_sums.
    //     Loads unconditional; cnt==0 rows redirect the address to the
    //     always-zero decoy (L1/L2-hot); writeback predicated on cnt!=0. ---
    {
        uint64_t pf = mkpol_first();
        float4* gp = (float4*)(g_sums + rowbase*C_);
        const float4* dp = (const float4*)g_dummy;
        float4 z = make_float4(0.f, 0.f, 0.f, 0.f);
        #pragma unroll
        for (int it = 0; it < 8; it++){
            int i = it*256 + tid;          // 2048 float4
            int row = i >> 4, c4 = i & 15; // 16 float4 per row (K=64)
            bool live = (sraw[row] != 0.0f);
            const float4* src = live ? (const float4*)(gp + i) : (dp + c4);
            float4 v = ldg_stream_v4(src, pf);      // always issued
            if (live) gp[i] = z;                    // store-side skip only
            float inv = scnt[row];
            float f0 = v.x*inv, f1 = v.y*inv, f2 = v.z*inv, f3 = v.w*inv;

            __half2 h01 = __floats2half2_rn(f0, f1);
            __half2 h23 = __floats2half2_rn(f2, f3);
            float2 hf01 = __half22float2(h01);
            float2 hf23 = __half22float2(h23);
            __half2 l01 = __floats2half2_rn(f0 - hf01.x, f1 - hf01.y);
            __half2 l23 = __floats2half2_rn(f2 - hf23.x, f3 - hf23.y);

            uint2 p0, p1;
            p0.x = *(uint32_t*)&h01; p0.y = *(uint32_t*)&l01;
            p1.x = *(uint32_t*)&h23; p1.y = *(uint32_t*)&l23;
            sA2[row*SA_STRIDE + c4*2    ] = p0;   // kpairs 2*c4, 2*c4+1
            sA2[row*SA_STRIDE + c4*2 + 1] = p1;
        }
    }
    __syncthreads();

    // --- mainloop: 4 k-steps of 16, 16 n-tiles, 2 passes (hi*B, lo*B) ---
    int warp = tid >> 5, lane = tid & 31;
    int g = lane >> 2, t = lane & 3;
    int r = warp*16 + g;                   // A rows r, r+8

    float c[16][4];
    #pragma unroll
    for (int nt = 0; nt < 16; nt++){
        c[nt][0]=0.f; c[nt][1]=0.f; c[nt][2]=0.f; c[nt][3]=0.f;
    }

    #pragma unroll
    for (int kc = 0; kc < 4; kc++){
        int kp0 = kc*8 + t;                // kpair for a0/a1
        int kp1 = kp0 + 4;                 // kpair for a2/a3
        uint2 A0 = sA2[(r  )*SA_STRIDE + kp0];
        uint2 A1 = sA2[(r+8)*SA_STRIDE + kp0];
        uint2 A2 = sA2[(r  )*SA_STRIDE + kp1];
        uint2 A3 = sA2[(r+8)*SA_STRIDE + kp1];
        int pi = kc*4 + t;

        #pragma unroll
        for (int nt = 0; nt < 16; nt++){
            int n = nt*8 + g;
            uint2 Bk = sB2[n*SB_STRIDE + pi];   // (b[kp0], b[kp1])
            MMA_F16(c[nt], A0.x,A1.x,A2.x,A3.x, Bk.x,Bk.y);  // hi * B
            MMA_F16(c[nt], A0.y,A1.y,A2.y,A3.y, Bk.x,Bk.y);  // lo * B
        }
    }

    // --- epilogue: + conf*W[64,:] + bias; evict_first float2 stores ---
    {
        uint64_t pf = mkpol_first();
        float cf0 = sconf[r], cf1 = sconf[r+8];
        float* o0 = out + (rowbase + r)*128;
        float* o1 = out + (rowbase + r + 8)*128;
        #pragma unroll
        for (int nt = 0; nt < 16; nt++){
            int col = nt*8 + 2*t;
            float w0 = sw64[col], w1 = sw64[col+1];
            float bv0 = sb[col],  bv1 = sb[col+1];
            float2 v0 = make_float2(c[nt][0] + cf0*w0 + bv0,
                                    c[nt][1] + cf0*w1 + bv1);
            float2 v1 = make_float2(c[nt][2] + cf1*w0 + bv0,
                                    c[nt][3] + cf1*w1 + bv1);
            stg_pol_v2(o0 + col, v0, pf);
            stg_pol_v2(o1 + col, v1, pf);
        }
    }
}

// ---------------------------------------------------------------------------
extern "C" void kernel_launch(void* const* d_in, const int* in_sizes, int n_in,
                              void* d_out, int out_size)
{
    (void)in_sizes; (void)n_in; (void)out_size;
    const float*    pose = (const float*)d_in[0];
    const float*    intr = (const float*)d_in[1];
    const float*    feat = (const float*)d_in[2];
    /* d_in[3] = depths, unused by the reference */
    const float*    conf = (const float*)d_in[4];
    const int*      vids = (const int*)d_in[5];
    const unsigned* mask = (const unsigned*)d_in[6];
    const float*    w_fc = (const float*)d_in[7];
    const float*    b_fc = (const float*)d_in[8];

    float* out  = (float*)d_out;                      // (B,V,OUT) first
    float* dout = out + (size_t)ROWS_*OUT_;           // then (B,N,H,W,3)

    int nblk = (B_*R_) / 256;                         // 3072, exact

    scatter_rays_kernel<<<nblk, 256>>>(feat, vids, mask, pose, intr, dout);
    prep_kernel<<<8, 256>>>(w_fc);

    cudaFuncSetAttribute(gemm_kernel,
                         cudaFuncAttributeMaxDynamicSharedMemorySize, SMEM_TOTAL);
    gemm_kernel<<<ROWS_/128, 256, SMEM_TOTAL>>>(conf, w_fc, b_fc, out);
}

// round 17
// speedup vs baseline: 1.5997x; 1.5997x over previous
#include <cuda_runtime.h>
#include <cuda_fp16.h>
#include <cstdint>

#define B_   2
#define N_   8
#define C_   64
#define H_   192
#define W_   256
#define V_   200000
#define HW_  (H_*W_)
#define R_   (N_*HW_)          // 393216
#define ROWS_ (B_*V_)          // 400000
#define OUT_ 128

// fp16 scatter accumulator: zero-initialized at module load; gemm re-zeroes
// live rows (cnt==0 rows were never written — their writeback is skipped).
__device__ __align__(16) __half g_sums[(size_t)ROWS_*C_];  // 51.2 MB
__device__ float g_cnt[ROWS_];
// Pre-split packed weights: per (n, pi): uint4(hi[kp0], hi[kp1], lo[kp0], lo[kp1]).
__device__ __align__(16) uint4 g_wB4[128*16];              // 32 KB

// ---------------- L2 policy / streaming load+store helpers ----------------
__device__ __forceinline__ uint64_t mkpol_first(){
    uint64_t p;
    asm("createpolicy.fractional.L2::evict_first.b64 %0, 1.0;" : "=l"(p));
    return p;
}
__device__ __forceinline__ float ldg_stream(const float* p, uint64_t pol){
    float v;
    asm("ld.global.nc.L2::cache_hint.f32 %0, [%1], %2;" : "=f"(v) : "l"(p), "l"(pol));
    return v;
}
__device__ __forceinline__ unsigned ldg_stream_u32(const unsigned* p, uint64_t pol){
    unsigned v;
    asm("ld.global.nc.L2::cache_hint.u32 %0, [%1], %2;" : "=r"(v) : "l"(p), "l"(pol));
    return v;
}
__device__ __forceinline__ uint4 ldg_stream_u4(const uint4* p, uint64_t pol){
    uint4 v;
    asm("ld.global.nc.L2::cache_hint.v4.u32 {%0,%1,%2,%3}, [%4], %5;"
        : "=r"(v.x), "=r"(v.y), "=r"(v.z), "=r"(v.w) : "l"(p), "l"(pol));
    return v;
}
__device__ __forceinline__ void stg_pol_f32(float* p, float v, uint64_t pol){
    asm volatile("st.global.L2::cache_hint.f32 [%0], %1, %2;"
                 :: "l"(p), "f"(v), "l"(pol) : "memory");
}
__device__ __forceinline__ void stg_pol_v2(float* p, float2 v, uint64_t pol){
    asm volatile("st.global.L2::cache_hint.v2.f32 [%0], {%1,%2}, %3;"
                 :: "l"(p), "f"(v.x), "f"(v.y), "l"(pol) : "memory");
}
__device__ __forceinline__ uint32_t packh2(float a, float b){
    __half2 h = __floats2half2_rn(a, b);
    return *(uint32_t*)&h;
}
// Vectorized fp16x2 reduction (sm_90+): 8 channels per op.
__device__ __forceinline__ void red_v4h(__half* p, uint32_t r0, uint32_t r1,
                                        uint32_t r2, uint32_t r3){
    asm volatile("red.global.add.noftz.v4.f16x2 [%0], {%1, %2, %3, %4};"
                 :: "l"(p), "r"(r0), "r"(r1), "r"(r2), "r"(r3) : "memory");
}

// fp16 m16n8k16, fp32 accumulate.
#define MMA_F16(c, a0,a1,a2,a3, b0,b1)                                        \
    asm volatile("mma.sync.aligned.m16n8k16.row.col.f32.f16.f16.f32 "         \
        "{%0,%1,%2,%3}, {%4,%5,%6,%7}, {%8,%9}, {%0,%1,%2,%3};"               \
        : "+f"((c)[0]), "+f"((c)[1]), "+f"((c)[2]), "+f"((c)[3])              \
        : "r"(a0), "r"(a1), "r"(a2), "r"(a3), "r"(b0), "r"(b1))

// ---------------------------------------------------------------------------
// Kernel 1: rays + masked scatter-add (fp16x2 atomics), fused.
// ---------------------------------------------------------------------------
__global__ void __launch_bounds__(256) scatter_rays_kernel(
    const float* __restrict__ feat,
    const int*   __restrict__ vids,
    const unsigned* __restrict__ mask,
    const float* __restrict__ pose,
    const float* __restrict__ intr,
    float* __restrict__ dout)
{
    int idx = blockIdx.x*blockDim.x + threadIdx.x;   // covers exactly B*R
    uint64_t pf = mkpol_first();

    // ---- rays ----
    {
        int w  = idx % W_;
        int h  = (idx / W_) % H_;
        int bn = idx / HW_;
        const float* p  = pose + bn*16;
        const float* it = intr + bn*6;
        float uu = ((float)w - it[2]) / it[0];
        float vv = ((float)h - it[3]) / it[1];
        float dx = p[0]*uu + p[1]*vv + p[2];
        float dy = p[4]*uu + p[5]*vv + p[6];
        float dz = p[8]*uu + p[9]*vv + p[10];
        float rn = rsqrtf(dx*dx + dy*dy + dz*dz);
        stg_pol_f32(dout + 3*idx + 0, dx*rn, pf);
        stg_pol_f32(dout + 3*idx + 1, dy*rn, pf);
        stg_pol_f32(dout + 3*idx + 2, dz*rn, pf);
    }

    // ---- scatter ----
    unsigned m = ldg_stream_u32(mask + idx, pf);     // fp32 1.0 / int32 1: nonzero
    if (__ballot_sync(0xffffffffu, m != 0u) == 0u) return;
    if (m == 0u) return;

    int b   = idx / R_;
    int vid = (int)ldg_stream_u32((const unsigned*)(vids + idx), pf);
    atomicAdd(&g_cnt[b*V_ + vid], 1.0f);

    int bn = idx / HW_;
    int hw = idx % HW_;
    const float* fp = feat + (size_t)bn*C_*HW_ + hw;
    __half* sp = g_sums + (size_t)(b*V_ + vid)*C_;

    float x[32];
    #pragma unroll
    for (int half = 0; half < 2; half++){
        int cb = half*32;
        #pragma unroll
        for (int c = 0; c < 32; c++)
            x[c] = ldg_stream(fp + (size_t)(cb + c)*HW_, pf);
        #pragma unroll
        for (int cg = 0; cg < 4; cg++){   // 8 channels per red.v4.f16x2
            uint32_t r0 = packh2(x[8*cg+0], x[8*cg+1]);
            uint32_t r1 = packh2(x[8*cg+2], x[8*cg+3]);
            uint32_t r2 = packh2(x[8*cg+4], x[8*cg+5]);
            uint32_t r3 = packh2(x[8*cg+6], x[8*cg+7]);
            red_v4h(sp + cb + 8*cg, r0, r1, r2, r3);
        }
    }
}

// ---------------------------------------------------------------------------
// Kernel 2: one-shot weight prep — fp16 hi/lo split, packed per (n, pi):
// uint4{ hi[kp0], hi[kp1], lo[kp0], lo[kp1] },  kp0 = kc*8+t, kp1 = kp0+4.
// ---------------------------------------------------------------------------
__global__ void prep_kernel(const float* __restrict__ w_fc)
{
    int i = blockIdx.x*blockDim.x + threadIdx.x;   // 2048 = 128n x 16pi
    int n = i >> 4, pi = i & 15;
    int kc = pi >> 2, t = pi & 3;
    int kp0 = kc*8 + t;
    int kp1 = kp0 + 4;

    float a0 = w_fc[(2*kp0+0)*128 + n], a1 = w_fc[(2*kp0+1)*128 + n];
    float b0 = w_fc[(2*kp1+0)*128 + n], b1 = w_fc[(2*kp1+1)*128 + n];
    __half2 h0 = __floats2half2_rn(a0, a1);
    __half2 h1 = __floats2half2_rn(b0, b1);
    float2 hf0 = __half22float2(h0);
    float2 hf1 = __half22float2(h1);
    __half2 l0 = __floats2half2_rn(a0 - hf0.x, a1 - hf0.y);
    __half2 l1 = __floats2half2_rn(b0 - hf1.x, b1 - hf1.y);
    uint4 p;
    p.x = *(uint32_t*)&h0;
    p.y = *(uint32_t*)&h1;
    p.z = *(uint32_t*)&l0;
    p.w = *(uint32_t*)&l1;
    g_wB4[i] = p;
}

// ---------------------------------------------------------------------------
// Kernel 3: GEMM, fp16 m16n8k16, 2-pass over B (A x B_hi + A x B_lo).
// A = raw fp16 sums (pure uint4 copy gmem->smem, loads unconditional,
// zero-writeback predicated on cnt!=0). 1/cnt applied in the EPILOGUE.
// ---------------------------------------------------------------------------
#define SA_STRIDE 36                        // uint per row (32 used), LDS.32 conflict-free
#define SB_STRIDE 20                        // uint4 per n (16 used), LDS.128 conflict-free
#define SM_A_OFF    0
#define SM_B_OFF    (128*SA_STRIDE*4)       // 18432
#define SM_SCNT     (SM_B_OFF + 128*SB_STRIDE*16)  // 18432+40960 = 59392
#define SM_SRAW     (SM_SCNT + 512)
#define SM_SCONF    (SM_SRAW + 512)
#define SM_SW64     (SM_SCONF + 512)
#define SM_SB       (SM_SW64 + 512)
#define SMEM_TOTAL  (SM_SB + 512)           // 61952 B

__global__ void __launch_bounds__(256, 2) gemm_kernel(
    const float* __restrict__ conf,
    const float* __restrict__ w_fc,
    const float* __restrict__ b_fc,
    float* __restrict__ out)
{
    extern __shared__ unsigned char sm[];
    uint32_t* sAu = (uint32_t*)(sm + SM_A_OFF);
    uint4*    sB4 = (uint4*)(sm + SM_B_OFF);
    float* scnt  = (float*)(sm + SM_SCNT);   // 1/max(cnt,1)
    float* sraw  = (float*)(sm + SM_SRAW);   // raw cnt (0 => row untouched)
    float* sconf = (float*)(sm + SM_SCONF);
    float* sw64  = (float*)(sm + SM_SW64);
    float* sb    = (float*)(sm + SM_SB);

    int tid = threadIdx.x;
    size_t rowbase = (size_t)blockIdx.x * 128;

    // --- phase 0: scalars (tid<128) + B copy (all threads, coalesced) ---
    if (tid < 128){
        float cv = g_cnt[rowbase + tid];
        if (cv != 0.0f) g_cnt[rowbase + tid] = 0.0f;   // store-side skip only
        sraw[tid]  = cv;
        scnt[tid]  = 1.0f / fmaxf(cv, 1.0f);
        sconf[tid] = conf[rowbase + tid];
        sw64[tid]  = w_fc[64*128 + tid];
        sb[tid]    = b_fc[tid];
    }
    #pragma unroll
    for (int it = 0; it < 8; it++){
        int j = it*256 + tid;              // 2048 uint4
        int n = j >> 4, pi = j & 15;
        sB4[n*SB_STRIDE + pi] = g_wB4[j];
    }
    __syncthreads();

    // --- phase 1: copy A tile (fp16, 128 rows x 128 B) gmem->smem.
    //     Loads unconditional & linear (MLP preserved); zero-writeback
    //     predicated on cnt!=0 (untouched rows already zero in DRAM). ---
    {
        uint64_t pf = mkpol_first();
        uint4* gp = (uint4*)(g_sums + rowbase*C_);
        uint4 z = make_uint4(0u, 0u, 0u, 0u);
        #pragma unroll
        for (int it = 0; it < 4; it++){
            int i = it*256 + tid;          // 1024 uint4 total
            uint4 v = ldg_stream_u4(gp + i, pf);   // batched
            int row = i >> 3, q = i & 7;   // 8 uint4 per row (64 halves)
            if (sraw[row] != 0.0f) gp[i] = z;      // store-side skip only
            *(uint4*)&sAu[row*SA_STRIDE + q*4] = v;
        }
    }
    __syncthreads();

    // --- mainloop: 4 k-steps of 16, 16 n-tiles, 2 passes (A*Bhi, A*Blo) ---
    int warp = tid >> 5, lane = tid & 31;
    int g = lane >> 2, t = lane & 3;
    int r = warp*16 + g;                   // A rows r, r+8

    float c[16][4];
    #pragma unroll
    for (int nt = 0; nt < 16; nt++){
        c[nt][0]=0.f; c[nt][1]=0.f; c[nt][2]=0.f; c[nt][3]=0.f;
    }

    #pragma unroll
    for (int kc = 0; kc < 4; kc++){
        int kp0 = kc*8 + t;                // fp16x2 pair index for a0/a1
        int kp1 = kp0 + 4;                 // pair index for a2/a3
        uint32_t A0 = sAu[(r  )*SA_STRIDE + kp0];
        uint32_t A1 = sAu[(r+8)*SA_STRIDE + kp0];
        uint32_t A2 = sAu[(r  )*SA_STRIDE + kp1];
        uint32_t A3 = sAu[(r+8)*SA_STRIDE + kp1];
        int pi = kc*4 + t;

        #pragma unroll
        for (int nt = 0; nt < 16; nt++){
            int n = nt*8 + g;
            uint4 Bk = sB4[n*SB_STRIDE + pi];   // {bh0, bh1, bl0, bl1}
            MMA_F16(c[nt], A0,A1,A2,A3, Bk.x, Bk.y);  // A * B_hi
            MMA_F16(c[nt], A0,A1,A2,A3, Bk.z, Bk.w);  // A * B_lo
        }
    }

    // --- epilogue: inv*(S@W) + conf*W[64,:] + bias; evict_first stores ---
    {
        uint64_t pf = mkpol_first();
        float inv0 = scnt[r],  inv1 = scnt[r+8];
        float cf0  = sconf[r], cf1  = sconf[r+8];
        float* o0 = out + (rowbase + r)*128;
        float* o1 = out + (rowbase + r + 8)*128;
        #pragma unroll
        for (int nt = 0; nt < 16; nt++){
            int col = nt*8 + 2*t;
            float w0 = sw64[col], w1 = sw64[col+1];
            float bv0 = sb[col],  bv1 = sb[col+1];
            float2 v0 = make_float2(c[nt][0]*inv0 + cf0*w0 + bv0,
                                    c[nt][1]*inv0 + cf0*w1 + bv1);
            float2 v1 = make_float2(c[nt][2]*inv1 + cf1*w0 + bv0,
                                    c[nt][3]*inv1 + cf1*w1 + bv1);
            stg_pol_v2(o0 + col, v0, pf);
            stg_pol_v2(o1 + col, v1, pf);
        }
    }
}

// ---------------------------------------------------------------------------
extern "C" void kernel_launch(void* const* d_in, const int* in_sizes, int n_in,
                              void* d_out, int out_size)
{
    (void)in_sizes; (void)n_in; (void)out_size;
    const float*    pose = (const float*)d_in[0];
    const float*    intr = (const float*)d_in[1];
    const float*    feat = (const float*)d_in[2];
    /* d_in[3] = depths, unused by the reference */
    const float*    conf = (const float*)d_in[4];
    const int*      vids = (const int*)d_in[5];
    const unsigned* mask = (const unsigned*)d_in[6];
    const float*    w_fc = (const float*)d_in[7];
    const float*    b_fc = (const float*)d_in[8];

    float* out  = (float*)d_out;                      // (B,V,OUT) first
    float* dout = out + (size_t)ROWS_*OUT_;           // then (B,N,H,W,3)

    int nblk = (B_*R_) / 256;                         // 3072, exact

    scatter_rays_kernel<<<nblk, 256>>>(feat, vids, mask, pose, intr, dout);
    prep_kernel<<<8, 256>>>(w_fc);

    cudaFuncSetAttribute(gemm_kernel,
                         cudaFuncAttributeMaxDynamicSharedMemorySize, SMEM_TOTAL);
    gemm_kernel<<<ROWS_/128, 256, SMEM_TOTAL>>>(conf, w_fc, b_fc, out);
}